// round 3
// baseline (speedup 1.0000x reference)
#include <cuda_runtime.h>
#include <cuda_bf16.h>

// MiscTypeChecker: [B=8192, S=8192] int32 tokens in [0,8), scalar output.
// rg1/rg2: first-two-token checks. rg3: (8 - n_unique)^2 per row.
// rg4: last occurrence of token 1; next 5 tokens vs [2,4,5,6,3], else 6.
//
// Strategy: backward suffix scan per row with early exit. Presence is monotone
// (suffix full => row full) and the first '1' found scanning backward IS the
// last occurrence. Expected work: one 512B chunk per row (~4.3 MB total read
// instead of 256 MB). Full-row fallback loop preserves exactness.
//
// Output written as float32 (exact: total < 2^24).

#define S_DIM 8192
#define TYPE_RANGE 8

__global__ void mtc_zero_kernel(float* __restrict__ out, int n) {
    int i = blockIdx.x * blockDim.x + threadIdx.x;
    if (i < n) out[i] = 0.0f;
}

__global__ void __launch_bounds__(256, 1)
mtc_row_kernel(const int* __restrict__ mpt, float* __restrict__ out, int B) {
    __shared__ int bsum;
    if (threadIdx.x == 0) bsum = 0;
    __syncthreads();

    const int warp = threadIdx.x >> 5;
    const int lane = threadIdx.x & 31;
    const int row  = blockIdx.x * 8 + warp;

    if (row < B) {
        const int* __restrict__ rp = mpt + (long long)row * S_DIM;

        unsigned pres = 0u;
        int last1 = -1;

        // Backward chunks of 128 elements: 32 lanes x int4 (coalesced 512B).
        for (int base = S_DIM - 128; base >= 0; base -= 128) {
            const int4 v = reinterpret_cast<const int4*>(rp + base)[lane];
            const int eb = base + lane * 4;

            // presence (with reference's clip to [0, TYPE_RANGE-1])
            const int cx = min(max(v.x, 0), TYPE_RANGE - 1);
            const int cy = min(max(v.y, 0), TYPE_RANGE - 1);
            const int cz = min(max(v.z, 0), TYPE_RANGE - 1);
            const int cw = min(max(v.w, 0), TYPE_RANGE - 1);
            unsigned p = (1u << cx) | (1u << cy) | (1u << cz) | (1u << cw);

            // highest position of token==1 within this thread's 4 elems
            int l = -1;
            if (v.x == 1) l = eb;
            if (v.y == 1) l = eb + 1;
            if (v.z == 1) l = eb + 2;
            if (v.w == 1) l = eb + 3;

            pres |= __reduce_or_sync(0xffffffffu, p);
            if (last1 < 0) {
                // first hit scanning backward == last occurrence in the row
                last1 = __reduce_max_sync(0xffffffffu, l);
            }
            if (pres == 0xFFu && last1 >= 0) break;  // uniform across warp
        }

        if (lane == 0) {
            const int t0 = rp[0];
            const int t1 = rp[1];
            int r = ((t0 != 0) + (t1 != 1)) * 4;

            const int miss = TYPE_RANGE - __popc(pres);
            r += miss * miss;

            int rg4 = 6;
            if (last1 > 0 && last1 < S_DIM - 5) {
                rg4 = (rp[last1 + 1] != 2) + (rp[last1 + 2] != 4) +
                      (rp[last1 + 3] != 5) + (rp[last1 + 4] != 6) +
                      (rp[last1 + 5] != 3);
            }
            atomicAdd(&bsum, r + rg4);
        }
    }

    __syncthreads();
    // One global float atomic per block (1024 total). Integer-valued floats,
    // total < 2^24, so the accumulation is exact.
    if (threadIdx.x == 0) atomicAdd(out, (float)bsum);
}

extern "C" void kernel_launch(void* const* d_in, const int* in_sizes, int n_in,
                              void* d_out, int out_size) {
    // The token matrix is the largest input (type_range may arrive as a
    // 1-element scalar input; we hardcode TYPE_RANGE=8 per problem spec).
    int big = 0;
    for (int i = 1; i < n_in; i++)
        if (in_sizes[i] > in_sizes[big]) big = i;

    const int* mpt = (const int*)d_in[big];
    float* out = (float*)d_out;
    const int B = in_sizes[big] / S_DIM;

    mtc_zero_kernel<<<(out_size + 255) / 256, 256>>>(out, out_size);
    mtc_row_kernel<<<(B + 7) / 8, 256>>>(mpt, out, B);
}